// round 10
// baseline (speedup 1.0000x reference)
#include <cuda_runtime.h>
#include <cstdint>

// TemporalCompressor: per-batch centered-window linear interpolation resample.
// encoded: [B, D, T] f32, ratio: [B] f32, out: [B, D, To] f32
//
// Persistent-CTA + double-buffered TMA bulk pipeline:
//   - 131072 tiles of 512 outputs; fixed grid of 1824 persistent blocks
//     (12/SM), grid-stride over tiles.
//   - Per tile: one cp.async.bulk stages the needed source sub-window
//     (<=4.13 KB) into SMEM. The load for tile t+stride is issued BEFORE
//     waiting on tile t's mbarrier, so TMA latency overlaps compute.
//   - Interpolate from SMEM; one float4 streaming store per thread.

static constexpr int B_   = 32;
static constexpr int D_   = 512;
static constexpr int T_   = 8192;
static constexpr int TO_  = 4096;
static constexpr int NT   = 128;           // threads per block
static constexpr int NC   = 8;             // chunks per row
static constexpr int C_   = TO_ / NC;      // 512 outputs per tile
static constexpr int SBUF = C_ * 2 + 8;    // 1032 floats per buffer (4.13 KB)
static constexpr int NTILES = NC * D_ * B_;    // 131072
static constexpr int NCTA   = 1824;            // 152 SMs * 12

struct TileParams {
    const float* grow;     // global source of staged window (16B aligned)
    float*       dst;      // output base for this tile
    uint32_t     bytes;    // staged bytes
    int          base;     // buf[base + idx] = window[idx]
    float        scale, Lm1f;
    int          Lm1, i0;
};

__device__ __forceinline__ TileParams tile_params(int tile,
                                                  const float* __restrict__ encoded,
                                                  const float* __restrict__ ratio,
                                                  float* __restrict__ out)
{
    const int chunk = tile & (NC - 1);
    const int rest  = tile >> 3;           // NC == 8
    const int d     = rest & (D_ - 1);
    const int b     = rest >> 9;           // D_ == 512

    const float r = __ldg(&ratio[b]);
    float Lf = floorf((float)TO_ * r);     // fp32 floor, exactly like reference
    int   L  = (int)Lf;
    if (L > T_) { L = T_; Lf = (float)T_; }
    const int   start = (T_ - L) >> 1;
    const float scale = Lf * (1.0f / (float)TO_);
    const float Lm1f  = (float)(L - 1);
    const int   Lm1   = L - 1;

    const int i0 = chunk * C_;

    // Window-relative source range needed by outputs [i0, i0+C_), using the
    // SAME clamped expression as the interp loop (monotonic in i).
    float x0 = fmaf((float)i0 + 0.5f, scale, -0.5f);
    x0 = fminf(fmaxf(x0, 0.0f), Lm1f);
    const int g0 = (int)x0;
    float x1 = fmaf((float)(i0 + C_ - 1) + 0.5f, scale, -0.5f);
    x1 = fminf(fmaxf(x1, 0.0f), Lm1f);
    const int g1 = min((int)x1 + 1, Lm1);

    // Align the absolute row offset down to 16B (row base is 16B aligned).
    const int s0        = start + g0;
    const int aligned_g = s0 & ~3;
    const int off       = s0 - aligned_g;              // 0..3
    int len = ((off + (g1 - g0 + 1) + 3) >> 2) << 2;   // round to 4 floats
    if (aligned_g + len > T_) len = T_ - aligned_g;    // row clamp (keeps %4)

    TileParams p;
    p.grow  = encoded + ((size_t)b * D_ + d) * T_ + aligned_g;
    p.dst   = out     + ((size_t)b * D_ + d) * TO_;
    p.bytes = (uint32_t)len * 4u;
    p.base  = off - g0;
    p.scale = scale; p.Lm1f = Lm1f; p.Lm1 = Lm1; p.i0 = i0;
    return p;
}

__global__ __launch_bounds__(NT, 12)
void temporal_compressor_kernel(const float* __restrict__ encoded,
                                const float* __restrict__ ratio,
                                float* __restrict__ out)
{
    __shared__ __align__(16) float buf[2][SBUF];
    __shared__ __align__(8)  unsigned long long mbar[2];

    const int tid = threadIdx.x;
    const uint32_t mb0 = (uint32_t)__cvta_generic_to_shared(&mbar[0]);
    const uint32_t mb1 = (uint32_t)__cvta_generic_to_shared(&mbar[1]);
    const uint32_t sb0 = (uint32_t)__cvta_generic_to_shared(&buf[0][0]);
    const uint32_t sb1 = (uint32_t)__cvta_generic_to_shared(&buf[1][0]);

    if (tid == 0) {
        asm volatile("mbarrier.init.shared.b64 [%0], %1;" :: "r"(mb0), "r"(1) : "memory");
        asm volatile("mbarrier.init.shared.b64 [%0], %1;" :: "r"(mb1), "r"(1) : "memory");
    }
    __syncthreads();

    const int tile0 = blockIdx.x;

    // Prologue: issue load for the first tile into stage 0.
    if (tile0 < NTILES && tid == 0) {
        TileParams p = tile_params(tile0, encoded, ratio, out);
        asm volatile("mbarrier.arrive.expect_tx.shared.b64 _, [%0], %1;"
                     :: "r"(mb0), "r"(p.bytes) : "memory");
        asm volatile("cp.async.bulk.shared::cta.global.mbarrier::complete_tx::bytes "
                     "[%0], [%1], %2, [%3];"
                     :: "r"(sb0), "l"(p.grow), "r"(p.bytes), "r"(mb0) : "memory");
    }

    int ph0 = 0, ph1 = 0;
    int it = 0;
    for (int tile = tile0; tile < NTILES; tile += NCTA, ++it) {
        const int s0 = it & 1;

        // Issue next tile's load into the other stage before waiting.
        const int ntile = tile + NCTA;
        if (ntile < NTILES && tid == 0) {
            TileParams np = tile_params(ntile, encoded, ratio, out);
            const uint32_t mbn = s0 ? mb0 : mb1;
            const uint32_t sbn = s0 ? sb0 : sb1;
            asm volatile("mbarrier.arrive.expect_tx.shared.b64 _, [%0], %1;"
                         :: "r"(mbn), "r"(np.bytes) : "memory");
            asm volatile("cp.async.bulk.shared::cta.global.mbarrier::complete_tx::bytes "
                         "[%0], [%1], %2, [%3];"
                         :: "r"(sbn), "l"(np.grow), "r"(np.bytes), "r"(mbn) : "memory");
        }

        // Wait for the current tile's data.
        {
            const uint32_t mbc = s0 ? mb1 : mb0;
            const uint32_t phase = (uint32_t)(s0 ? ph1 : ph0);
            uint32_t done;
            do {
                asm volatile(
                    "{\n\t.reg .pred p;\n\t"
                    "mbarrier.try_wait.parity.acquire.cta.shared::cta.b64 p, [%1], %2, 0x989680;\n\t"
                    "selp.b32 %0, 1, 0, p;\n\t}"
                    : "=r"(done) : "r"(mbc), "r"(phase) : "memory");
            } while (!done);
            if (s0) ph1 ^= 1; else ph0 ^= 1;
        }

        // Compute this tile (params recomputed by all threads; deterministic).
        TileParams p = tile_params(tile, encoded, ratio, out);
        const float* __restrict__ bf = buf[s0];

        const int i_base = p.i0 + tid * 4;
        float res[4];
#pragma unroll
        for (int k = 0; k < 4; ++k) {
            const int i = i_base + k;
            float x = fmaf((float)i + 0.5f, p.scale, -0.5f);
            x = fminf(fmaxf(x, 0.0f), p.Lm1f);
            const int   lo = (int)x;                 // x >= 0 -> trunc == floor
            const int   hi = min(lo + 1, p.Lm1);
            const float w  = x - (float)lo;
            const float g_lo = bf[p.base + lo];
            const float g_hi = bf[p.base + hi];
            res[k] = fmaf(g_hi - g_lo, w, g_lo);     // g_lo*(1-w) + g_hi*w
        }
        __stcs(reinterpret_cast<float4*>(p.dst + i_base),
               make_float4(res[0], res[1], res[2], res[3]));

        // All threads done reading buf[s0] before it is re-targeted next iter.
        __syncthreads();
    }
}

extern "C" void kernel_launch(void* const* d_in, const int* in_sizes, int n_in,
                              void* d_out, int out_size)
{
    const float* encoded = (const float*)d_in[0];
    const float* ratio   = (const float*)d_in[1];
    float* out           = (float*)d_out;

    temporal_compressor_kernel<<<NCTA, NT>>>(encoded, ratio, out);
}

// round 11
// speedup vs baseline: 1.1407x; 1.1407x over previous
#include <cuda_runtime.h>
#include <cstdint>

// TemporalCompressor: per-batch centered-window linear interpolation resample.
// encoded: [B, D, T] f32, ratio: [B] f32, out: [B, D, To] f32
//
// Strategy (best-known, round-8 structure + trimmed critical path):
// 4 blocks per (b, d) row, each owning 1024 consecutive outputs.
// Input sub-window (<=8.2 KB) staged into SMEM with ONE cp.async.bulk +
// mbarrier (init + issue by thread 0, ONE syncthreads, then wait);
// interpolate from SMEM; float4 streaming stores. 16 CTAs/SM.

static constexpr int B_   = 32;
static constexpr int D_   = 512;
static constexpr int T_   = 8192;
static constexpr int TO_  = 4096;
static constexpr int NT   = 128;           // threads per block
static constexpr int NC   = 4;             // chunks per row
static constexpr int C_   = TO_ / NC;      // 1024 outputs per block
static constexpr int V4   = C_ / (NT * 4); // 2 float4 groups per thread
static constexpr int SBUF = C_ * 2 + 8;    // max window floats (2050) + pad

__global__ __launch_bounds__(NT, 16)
void temporal_compressor_kernel(const float* __restrict__ encoded,
                                const float* __restrict__ ratio,
                                float* __restrict__ out)
{
    __shared__ __align__(16) float buf[SBUF];              // 8.26 KB input tile
    __shared__ __align__(8)  unsigned long long mbar;

    const int chunk = blockIdx.x;          // 0..NC-1
    const int d     = blockIdx.y;
    const int b     = blockIdx.z;
    const int tid   = threadIdx.x;

    // Per-batch window parameters (uniform across block)
    const float r = __ldg(&ratio[b]);
    float Lf = floorf((float)TO_ * r);     // fp32 floor, exactly like reference
    int   L  = (int)Lf;
    if (L > T_) { L = T_; Lf = (float)T_; }
    const int   start = (T_ - L) >> 1;
    const float scale = Lf * (1.0f / (float)TO_);
    const float Lm1f  = (float)(L - 1);
    const int   Lm1   = L - 1;

    const int i0 = chunk * C_;

    // Source sub-window [g0, g1] (window-relative) needed by outputs
    // [i0, i0+C_), computed with the SAME clamped expression as the interp
    // loop (x is monotonic in i, so endpoints bound everything between).
    float x0 = fmaf((float)i0 + 0.5f, scale, -0.5f);
    x0 = fminf(fmaxf(x0, 0.0f), Lm1f);
    const int g0 = (int)x0;
    float x1 = fmaf((float)(i0 + C_ - 1) + 0.5f, scale, -0.5f);
    x1 = fminf(fmaxf(x1, 0.0f), Lm1f);
    const int g1 = min((int)x1 + 1, Lm1);

    // Absolute row offset of window start; align DOWN to 16B within the row.
    // Row base (multiple of T_ floats) is 16B-aligned, so row+aligned_g is too.
    const int s0        = start + g0;
    const int aligned_g = s0 & ~3;
    const int off       = s0 - aligned_g;              // 0..3
    int len = ((off + (g1 - g0 + 1) + 3) >> 2) << 2;   // round up to 4 floats
    if (aligned_g + len > T_) len = T_ - aligned_g;    // row clamp (keeps %4)

    const float* __restrict__ grow = encoded + ((size_t)b * D_ + d) * T_ + aligned_g;
    float* __restrict__ dst        = out     + ((size_t)b * D_ + d) * TO_;

    // ---- Stage sub-window into SMEM via one TMA bulk copy ----
    // Thread 0 inits the mbarrier AND issues the load; the single
    // __syncthreads below orders init before every thread's try_wait.
    const uint32_t mbar_addr = (uint32_t)__cvta_generic_to_shared(&mbar);
    const uint32_t sbuf_addr = (uint32_t)__cvta_generic_to_shared(buf);
    const uint32_t bytes     = (uint32_t)len * 4u;

    if (tid == 0) {
        asm volatile("mbarrier.init.shared.b64 [%0], %1;"
                     :: "r"(mbar_addr), "r"(1) : "memory");
        asm volatile("mbarrier.arrive.expect_tx.shared.b64 _, [%0], %1;"
                     :: "r"(mbar_addr), "r"(bytes) : "memory");
        asm volatile("cp.async.bulk.shared::cta.global.mbarrier::complete_tx::bytes "
                     "[%0], [%1], %2, [%3];"
                     :: "r"(sbuf_addr), "l"(grow), "r"(bytes), "r"(mbar_addr)
                     : "memory");
    }
    __syncthreads();
    // All threads wait on the mbarrier (parity 0; smem is fresh every launch)
    {
        uint32_t done;
        do {
            asm volatile(
                "{\n\t.reg .pred p;\n\t"
                "mbarrier.try_wait.parity.acquire.cta.shared::cta.b64 p, [%1], %2, 0x989680;\n\t"
                "selp.b32 %0, 1, 0, p;\n\t}"
                : "=r"(done) : "r"(mbar_addr), "r"(0u) : "memory");
        } while (!done);
    }

    // buf[k] = row[aligned_g + k]  ->  window[idx] = buf[idx - g0 + off]
    const int base = off - g0;

    // ---- Interpolate from SMEM, float4 streaming stores ----
#pragma unroll
    for (int v = 0; v < V4; ++v) {
        const int i_base = i0 + (tid + v * NT) * 4;
        // x for k=0; subsequent k via incremental add (x is affine in i)
        float xb = fmaf((float)i_base + 0.5f, scale, -0.5f);
        float res[4];
#pragma unroll
        for (int k = 0; k < 4; ++k) {
            float x = fminf(fmaxf(xb, 0.0f), Lm1f);
            xb += scale;
            const int   lo = (int)x;                 // x >= 0 -> trunc == floor
            const int   hi = min(lo + 1, Lm1);
            const float w  = x - (float)lo;
            const float g_lo = buf[base + lo];
            const float g_hi = buf[base + hi];
            res[k] = fmaf(g_hi - g_lo, w, g_lo);     // g_lo*(1-w) + g_hi*w
        }
        __stcs(reinterpret_cast<float4*>(dst + i_base),
               make_float4(res[0], res[1], res[2], res[3]));
    }
}

extern "C" void kernel_launch(void* const* d_in, const int* in_sizes, int n_in,
                              void* d_out, int out_size)
{
    const float* encoded = (const float*)d_in[0];
    const float* ratio   = (const float*)d_in[1];
    float* out           = (float*)d_out;

    dim3 block(NT, 1, 1);
    dim3 grid(NC, D_, B_);   // (4, 512, 32) = 65536 blocks
    temporal_compressor_kernel<<<grid, block>>>(encoded, ratio, out);
}